// round 5
// baseline (speedup 1.0000x reference)
#include <cuda_runtime.h>

// Shapes (fixed by the problem)
#define TT 2048
#define BB 1024
#define II 4
#define HH 10
#define OO 4

typedef unsigned long long ull;

// ---- Blackwell packed f32x2 helpers ----
__device__ __forceinline__ ull pk2(float lo, float hi) {
    ull r; asm("mov.b64 %0, {%1, %2};" : "=l"(r) : "f"(lo), "f"(hi)); return r;
}
__device__ __forceinline__ void upk2(ull v, float& lo, float& hi) {
    asm("mov.b64 {%0, %1}, %2;" : "=f"(lo), "=f"(hi) : "l"(v));
}
__device__ __forceinline__ ull fma2(ull a, ull b, ull c) {
    ull d; asm("fma.rn.f32x2 %0, %1, %2, %3;" : "=l"(d) : "l"(a), "l"(b), "l"(c)); return d;
}
__device__ __forceinline__ ull mul2(ull a, ull b) {
    ull d; asm("mul.rn.f32x2 %0, %1, %2;" : "=l"(d) : "l"(a), "l"(b)); return d;
}
__device__ __forceinline__ ull add2(ull a, ull b) {
    ull d; asm("add.rn.f32x2 %0, %1, %2;" : "=l"(d) : "l"(a), "l"(b)); return d;
}
__device__ __forceinline__ float ex2f(float x) {
    float r; asm("ex2.approx.f32 %0, %1;" : "=f"(r) : "f"(x)); return r;
}
__device__ __forceinline__ float rcpf(float x) {
    float r; asm("rcp.approx.f32 %0, %1;" : "=f"(r) : "f"(x)); return r;
}

// sigmoid of packed pre-activation that was PRE-SCALED by -log2e:
//   s = 1 / (1 + 2^a)   (per half; ex2/rcp are ~1-ulp accurate)
__device__ __forceinline__ ull sig2(ull a) {
    float lo, hi; upk2(a, lo, hi);
    float sl = rcpf(1.0f + ex2f(lo));
    float sh = rcpf(1.0f + ex2f(hi));
    return pk2(sl, sh);
}
// tanh of packed pre-activation PRE-SCALED by 2*log2e:
//   t = 1 - 2 / (1 + 2^a)
__device__ __forceinline__ ull tanhs2(ull a, ull NEG22, ull ONE2) {
    float lo, hi; upk2(a, lo, hi);
    float rl = rcpf(1.0f + ex2f(lo));
    float rh = rcpf(1.0f + ex2f(hi));
    return fma2(pk2(rl, rh), NEG22, ONE2);
}

// Layout: lane = (group grp=lane/10 in {0,1,2}, unit j=lane%10); lanes 30,31 idle.
// Each warp handles SIX batches: lane carries the packed pair
// (batch bA = warp*6+grp, batch bB = bA+3) for hidden unit j.
// All gate math is f32x2 (FFMA2); h exchanged via 2 scalar shfls per k.
__global__ void __launch_bounds__(128, 1)
lstm_fused2(const float* __restrict__ x,
            const float* __restrict__ h0,
            const float* __restrict__ c0,
            const float* __restrict__ Wih,
            const float* __restrict__ Whh,
            const float* __restrict__ bih,
            const float* __restrict__ bhh,
            const float* __restrict__ Wfc,
            const float* __restrict__ bfc,
            float* __restrict__ out)
{
    const int lane = threadIdx.x & 31;
    const int warp = blockIdx.x * 4 + (threadIdx.x >> 5);
    const int grp  = lane / 10;
    const int j    = lane - grp * 10;
    const int bA   = warp * 6 + grp;
    const int bB   = bA + 3;
    const bool validA = (grp < 3) && (bA < BB);
    const bool validB = (grp < 3) && (bB < BB);
    const int bAl = validA ? bA : 0;
    const int bBl = validB ? bB : 0;

    const float SGI = -1.4426950408889634f;  // sigmoid prescale  (-log2 e)
    const float SGG =  2.8853900817779268f;  // tanh prescale     (2 log2 e)

    // ---- weights, prescaled and duplicated into packed pairs ----
    ull wih2[4][II], whh2[4][HH], bias2[4];
#pragma unroll
    for (int g = 0; g < 4; g++) {
        const float sc = (g == 2) ? SGG : SGI;
        const int row = g * HH + j;                  // PyTorch order i,f,g,o
        const float b = (bih[row] + bhh[row]) * sc;
        bias2[g] = pk2(b, b);
#pragma unroll
        for (int i = 0; i < II; i++) {
            const float w = Wih[row * II + i] * sc;
            wih2[g][i] = pk2(w, w);
        }
#pragma unroll
        for (int k = 0; k < HH; k++) {
            const float w = Whh[row * HH + k] * sc;
            whh2[g][k] = pk2(w, w);
        }
    }
    ull wfc2[HH], bfc2;
    {
        const int o = (j < OO) ? j : 0;
#pragma unroll
        for (int k = 0; k < HH; k++) {
            const float w = Wfc[o * HH + k];
            wfc2[k] = pk2(w, w);
        }
        const float b = bfc[o];
        bfc2 = pk2(b, b);
    }

    const ull ONE2  = pk2(1.0f, 1.0f);
    const ull NEG22 = pk2(-2.0f, -2.0f);
    const ull SCC2  = pk2(SGG, SGG);

    float hA = h0[bAl * HH + j];
    float hB = h0[bBl * HH + j];
    ull c2 = pk2(c0[bAl * HH + j], c0[bBl * HH + j]);

    int src[HH];
    const int base = grp * 10;
#pragma unroll
    for (int k = 0; k < HH; k++) src[k] = base + k;  // grp 3 wraps, harmless

    const bool do_out = (grp < 3) && (j < OO);

    // depth-2 x prefetch, one broadcast float4 per batch per step
    const float4* xp = reinterpret_cast<const float4*>(x);
    float4 xa[2], xb[2];
    xa[0] = xp[0 * BB + bAl]; xb[0] = xp[0 * BB + bBl];
    xa[1] = xp[1 * BB + bAl]; xb[1] = xp[1 * BB + bBl];

#pragma unroll 2
    for (int t = 0; t < TT; t++) {
        const float4 xA = xa[t & 1];
        const float4 xB = xb[t & 1];
        const int tpre = (t + 2 < TT) ? (t + 2) : (TT - 1);
        xa[t & 1] = xp[tpre * BB + bAl];
        xb[t & 1] = xp[tpre * BB + bBl];

        const ull xx = pk2(xA.x, xB.x);
        const ull xy = pk2(xA.y, xB.y);
        const ull xz = pk2(xA.z, xB.z);
        const ull xw = pk2(xA.w, xB.w);

        // gate pre-activations: bias + W_ih @ x_t   (independent of h -> issues early)
        ull aP0 = fma2(wih2[0][0], xx, bias2[0]);
        ull aP1 = fma2(wih2[1][0], xx, bias2[1]);
        ull aP2 = fma2(wih2[2][0], xx, bias2[2]);
        ull aP3 = fma2(wih2[3][0], xx, bias2[3]);
        aP0 = fma2(wih2[0][1], xy, aP0);
        aP1 = fma2(wih2[1][1], xy, aP1);
        aP2 = fma2(wih2[2][1], xy, aP2);
        aP3 = fma2(wih2[3][1], xy, aP3);
        aP0 = fma2(wih2[0][2], xz, aP0);
        aP1 = fma2(wih2[1][2], xz, aP1);
        aP2 = fma2(wih2[2][2], xz, aP2);
        aP3 = fma2(wih2[3][2], xz, aP3);
        aP0 = fma2(wih2[0][3], xw, aP0);
        aP1 = fma2(wih2[1][3], xw, aP1);
        aP2 = fma2(wih2[2][3], xw, aP2);
        aP3 = fma2(wih2[3][3], xw, aP3);

        // + W_hh @ h_{t-1} (split k=0..4 / k=5..9 to halve chain depth)
        // FC output for step t-1 rides along in ao.
        ull aQ0, aQ1, aQ2, aQ3;
        ull ao = bfc2;
#pragma unroll
        for (int k = 0; k < HH; k++) {
            const float hkA = __shfl_sync(0xffffffffu, hA, src[k]);
            const float hkB = __shfl_sync(0xffffffffu, hB, src[k]);
            const ull hk2 = pk2(hkA, hkB);
            if (k == 0) {
                aQ0 = mul2(whh2[0][0], hk2);
                aQ1 = mul2(whh2[1][0], hk2);
                aQ2 = mul2(whh2[2][0], hk2);
                aQ3 = mul2(whh2[3][0], hk2);
            } else if (k < 5) {
                aQ0 = fma2(whh2[0][k], hk2, aQ0);
                aQ1 = fma2(whh2[1][k], hk2, aQ1);
                aQ2 = fma2(whh2[2][k], hk2, aQ2);
                aQ3 = fma2(whh2[3][k], hk2, aQ3);
            } else {
                aP0 = fma2(whh2[0][k], hk2, aP0);
                aP1 = fma2(whh2[1][k], hk2, aP1);
                aP2 = fma2(whh2[2][k], hk2, aP2);
                aP3 = fma2(whh2[3][k], hk2, aP3);
            }
            ao = fma2(wfc2[k], hk2, ao);
        }
        const ull a0 = add2(aP0, aQ0);
        const ull a1 = add2(aP1, aQ1);
        const ull a2 = add2(aP2, aQ2);
        const ull a3 = add2(aP3, aQ3);

        if (do_out && t > 0) {
            float aoA, aoB; upk2(ao, aoA, aoB);
            if (validA) out[((t - 1) * BB + bA) * OO + j] = aoA;
            if (validB) out[((t - 1) * BB + bB) * OO + j] = aoB;
        }

        const ull ig = sig2(a0);
        const ull fg = sig2(a1);
        const ull gg = tanhs2(a2, NEG22, ONE2);
        const ull og = sig2(a3);
        c2 = fma2(fg, c2, mul2(ig, gg));
        const ull tc = tanhs2(mul2(c2, SCC2), NEG22, ONE2);
        const ull h2 = mul2(og, tc);
        upk2(h2, hA, hB);
    }

    // tail: FC output for the final step
    {
        ull ao = bfc2;
#pragma unroll
        for (int k = 0; k < HH; k++) {
            const float hkA = __shfl_sync(0xffffffffu, hA, src[k]);
            const float hkB = __shfl_sync(0xffffffffu, hB, src[k]);
            ao = fma2(wfc2[k], pk2(hkA, hkB), ao);
        }
        if (do_out) {
            float aoA, aoB; upk2(ao, aoA, aoB);
            if (validA) out[((TT - 1) * BB + bA) * OO + j] = aoA;
            if (validB) out[((TT - 1) * BB + bB) * OO + j] = aoB;
        }
    }

    // final states hT, cT appended after out: [B,H] each
    {
        float cA, cB; upk2(c2, cA, cB);
        if (validA) {
            out[TT * BB * OO + bA * HH + j] = hA;
            out[TT * BB * OO + BB * HH + bA * HH + j] = cA;
        }
        if (validB) {
            out[TT * BB * OO + bB * HH + j] = hB;
            out[TT * BB * OO + BB * HH + bB * HH + j] = cB;
        }
    }
}

extern "C" void kernel_launch(void* const* d_in, const int* in_sizes, int n_in,
                              void* d_out, int out_size) {
    const float* x   = (const float*)d_in[0];
    const float* h0  = (const float*)d_in[1];
    const float* c0  = (const float*)d_in[2];
    const float* Wih = (const float*)d_in[3];
    const float* Whh = (const float*)d_in[4];
    const float* bih = (const float*)d_in[5];
    const float* bhh = (const float*)d_in[6];
    const float* Wfc = (const float*)d_in[7];
    const float* bfc = (const float*)d_in[8];

    // 171 useful warps (6 batches each) -> 43 blocks of 4 warps; at most one
    // block per SM, so every warp owns its SMSP. Fully warp-synchronous.
    lstm_fused2<<<43, 128>>>(x, h0, c0, Wih, Whh, bih, bhh, Wfc, bfc,
                             (float*)d_out);
}

// round 6
// speedup vs baseline: 1.4811x; 1.4811x over previous
#include <cuda_runtime.h>

// Shapes (fixed by the problem)
#define TT 2048
#define BB 1024
#define II 4
#define HH 10
#define OO 4

#define CHUNK 32          // steps between producer/consumer barriers
#define RING  64          // smem ring depth (2 chunks, double-buffered)

__device__ __forceinline__ float ex2f(float x) {
    float r; asm("ex2.approx.f32 %0, %1;" : "=f"(r) : "f"(x)); return r;
}
__device__ __forceinline__ float rcpf(float x) {
    float r; asm("rcp.approx.f32 %0, %1;" : "=f"(r) : "f"(x)); return r;
}
__device__ __forceinline__ void barpair(int id) {
    asm volatile("bar.sync %0, 64;" :: "r"(id) : "memory");
}

// Block = 256 threads = 8 warps.
//   Warps 0-3 : LSTM recurrence ("producer"), 3 batches each (lane = grp*10+j,
//               grp in {0,1,2}, j = hidden unit; lanes 30,31 idle).
//   Warps 4-7 : FC epilogue ("consumer") for the paired producer warp.
// Producer w writes h (30 floats) per step into hring[w][t%RING]; every CHUNK
// steps the pair meets at named barrier (1+w). Consumer computes
// out = W_fc @ h + b_fc for the chunk and stores it. BAR.SYNC drains STS, so
// no extra fencing is needed. Fully warp-synchronous otherwise.
__global__ void __launch_bounds__(256, 1)
lstm_split(const float* __restrict__ x,
           const float* __restrict__ h0,
           const float* __restrict__ c0,
           const float* __restrict__ Wih,
           const float* __restrict__ Whh,
           const float* __restrict__ bih,
           const float* __restrict__ bhh,
           const float* __restrict__ Wfc,
           const float* __restrict__ bfc,
           float* __restrict__ out)
{
    __shared__ __align__(16) float hring[4][RING][30];

    const int lane = threadIdx.x & 31;
    const int wid  = threadIdx.x >> 5;          // 0..7
    const int pw   = wid & 3;                   // producer index within block
    const int gw   = blockIdx.x * 4 + pw;       // global producer-warp id
    const int grp  = lane / 10;                 // 0..3 (3 => idle lanes 30,31)
    const int j    = lane - grp * 10;           // hidden unit / out col
    const int batch = gw * 3 + grp;
    const bool valid = (grp < 3) && (batch < BB);
    const int bl = valid ? batch : 0;

    const float SGI = -1.4426950408889634f;     // sigmoid prescale (-log2 e)
    const float SGG =  2.8853900817779268f;     // tanh prescale    (2 log2 e)

    if (wid < 4) {
        // ================= producer: LSTM recurrence =================
        float wih[4][II], whh[4][HH], bias[4];
#pragma unroll
        for (int g = 0; g < 4; g++) {
            const float sc = (g == 2) ? SGG : SGI;
            const int row = g * HH + j;          // PyTorch order i,f,g,o
            bias[g] = (bih[row] + bhh[row]) * sc;
#pragma unroll
            for (int i = 0; i < II; i++) wih[g][i] = Wih[row * II + i] * sc;
#pragma unroll
            for (int k = 0; k < HH; k++) whh[g][k] = Whh[row * HH + k] * sc;
        }

        float h  = h0[bl * HH + j];
        float cs = c0[bl * HH + j] * SGG;        // c kept in tanh-scaled domain

        int src[HH];
        const int base = grp * 10;
#pragma unroll
        for (int k = 0; k < HH; k++) src[k] = base + k;   // grp3 wraps, harmless

        // depth-2 x prefetch: one broadcast float4 per step
        const float4* xp = reinterpret_cast<const float4*>(x);
        float4 xbuf[2];
        xbuf[0] = xp[0 * BB + bl];
        xbuf[1] = xp[1 * BB + bl];

#pragma unroll 2
        for (int t = 0; t < TT; t++) {
            const float4 xv = xbuf[t & 1];
            const int tpre = (t + 2 < TT) ? (t + 2) : (TT - 1);
            xbuf[t & 1] = xp[tpre * BB + bl];

            // P = bias + W_ih @ x_t  (independent of h, issues during stalls)
            float P0 = fmaf(wih[0][0], xv.x, bias[0]);
            float P1 = fmaf(wih[1][0], xv.x, bias[1]);
            float P2 = fmaf(wih[2][0], xv.x, bias[2]);
            float P3 = fmaf(wih[3][0], xv.x, bias[3]);
            P0 = fmaf(wih[0][1], xv.y, P0);
            P1 = fmaf(wih[1][1], xv.y, P1);
            P2 = fmaf(wih[2][1], xv.y, P2);
            P3 = fmaf(wih[3][1], xv.y, P3);
            P0 = fmaf(wih[0][2], xv.z, P0);
            P1 = fmaf(wih[1][2], xv.z, P1);
            P2 = fmaf(wih[2][2], xv.z, P2);
            P3 = fmaf(wih[3][2], xv.z, P3);
            P0 = fmaf(wih[0][3], xv.w, P0);
            P1 = fmaf(wih[1][3], xv.w, P1);
            P2 = fmaf(wih[2][3], xv.w, P2);
            P3 = fmaf(wih[3][3], xv.w, P3);

            // + W_hh @ h_{t-1}, split into two 5-deep chains (Q: k0-4, P: k5-9)
            float Q0, Q1, Q2, Q3;
#pragma unroll
            for (int k = 0; k < HH; k++) {
                const float hk = __shfl_sync(0xffffffffu, h, src[k]);
                if (k == 0) {
                    Q0 = whh[0][0] * hk;
                    Q1 = whh[1][0] * hk;
                    Q2 = whh[2][0] * hk;
                    Q3 = whh[3][0] * hk;
                } else if (k < 5) {
                    Q0 = fmaf(whh[0][k], hk, Q0);
                    Q1 = fmaf(whh[1][k], hk, Q1);
                    Q2 = fmaf(whh[2][k], hk, Q2);
                    Q3 = fmaf(whh[3][k], hk, Q3);
                } else {
                    P0 = fmaf(whh[0][k], hk, P0);
                    P1 = fmaf(whh[1][k], hk, P1);
                    P2 = fmaf(whh[2][k], hk, P2);
                    P3 = fmaf(whh[3][k], hk, P3);
                }
            }
            const float a0 = P0 + Q0;   // i  (prescaled by -log2e)
            const float a1 = P1 + Q1;   // f  (prescaled by -log2e)
            const float a2 = P2 + Q2;   // g  (prescaled by 2log2e)
            const float a3 = P3 + Q3;   // o  (prescaled by -log2e)

            // activations with paired reciprocals (8 MUFU instead of 10):
            //   sigmoid(v) = 1/(1+2^a),  tanh(v) = 1 - 2/(1+2^a)
            const float pi = 1.0f + ex2f(a0);
            const float pf = 1.0f + ex2f(a1);
            const float pg = 1.0f + ex2f(a2);
            const float po = 1.0f + ex2f(a3);
            const float rif = rcpf(pi * pf);
            const float ig  = rif * pf;          // 1/pi
            const float fg  = rif * pi;          // 1/pf
            const float rgo = rcpf(pg * po);
            const float rg  = rgo * po;          // 1/pg
            const float og  = rgo * pg;          // 1/po
            const float ggS = fmaf(-2.0f * SGG, rg, SGG);   // tanh(g)*SGG
            cs = fmaf(fg, cs, ig * ggS);         // scaled-domain cell update
            const float tc = fmaf(-2.0f, rcpf(1.0f + ex2f(cs)), 1.0f);
            h = og * tc;

            if (lane < 30) hring[pw][t & (RING - 1)][lane] = h;
            if ((t & (CHUNK - 1)) == (CHUNK - 1)) barpair(1 + pw);
        }

        // final states hT, cT appended after out: [B,H] each
        if (valid) {
            out[TT * BB * OO + batch * HH + j] = h;
            out[TT * BB * OO + BB * HH + batch * HH + j] =
                cs * (1.0f / SGG);
        }
    } else {
        // ================= consumer: FC epilogue =================
        const bool act = (grp < 3) && (j < OO) && (batch < BB);
        float wfc[HH], bfcv;
        {
            const int o = (j < OO) ? j : 0;
#pragma unroll
            for (int k = 0; k < HH; k++) wfc[k] = Wfc[o * HH + k];
            bfcv = bfc[o];
        }
        const int hoff = (grp < 3) ? grp * 10 : 0;

        for (int cchunk = 0; cchunk < TT / CHUNK; cchunk++) {
            barpair(1 + pw);
            const int s0 = cchunk * CHUNK;
#pragma unroll 4
            for (int s = s0; s < s0 + CHUNK; s++) {
                const float2* hp = reinterpret_cast<const float2*>(
                    &hring[pw][s & (RING - 1)][hoff]);
                float acc = bfcv;
#pragma unroll
                for (int k = 0; k < 5; k++) {
                    const float2 hv = hp[k];
                    acc = fmaf(wfc[2 * k], hv.x, acc);
                    acc = fmaf(wfc[2 * k + 1], hv.y, acc);
                }
                if (act) out[(s * BB + batch) * OO + j] = acc;
            }
        }
    }
}

extern "C" void kernel_launch(void* const* d_in, const int* in_sizes, int n_in,
                              void* d_out, int out_size) {
    const float* x   = (const float*)d_in[0];
    const float* h0  = (const float*)d_in[1];
    const float* c0  = (const float*)d_in[2];
    const float* Wih = (const float*)d_in[3];
    const float* Whh = (const float*)d_in[4];
    const float* bih = (const float*)d_in[5];
    const float* bhh = (const float*)d_in[6];
    const float* Wfc = (const float*)d_in[7];
    const float* bfc = (const float*)d_in[8];

    // 86 blocks x 8 warps: 344 producer warps (3 batches each, covers 1024),
    // one producer + one consumer per SMSP, one block per SM.
    lstm_split<<<86, 256>>>(x, h0, c0, Wih, Whh, bih, bhh, Wfc, bfc,
                            (float*)d_out);
}